// round 1
// baseline (speedup 1.0000x reference)
#include <cuda_runtime.h>
#include <math.h>

// Problem constants
#define MTOT   80000      // 2 * 40000 rows (batch flattened)
#define NBATCH 2
#define NPB    40000      // rows per batch
#define DIN    1024
#define LDIM   512
#define DDIM   384
#define NDT    6          // D tiles of 64 in gemm2
#define NCHUNK 157        // ceil(40000/256)

// Scratch (device globals — no allocation)
__device__ float g_h[(size_t)MTOT * LDIM];        // 164 MB: relu(x@Wf+bf)
__device__ float g_spart[(size_t)NDT * MTOT];     // partial s per D-tile
__device__ float g_s[MTOT];                       // attention scores
__device__ float g_bmax[NBATCH * NCHUNK];
__device__ float g_maxv[NBATCH];
__device__ float g_Upart[(size_t)NBATCH * NCHUNK * LDIM];
__device__ float g_Zpart[NBATCH * NCHUNK];

// ---------------------------------------------------------------------------
// GEMM1: h = relu(x @ Wf + bf).  M=80000, K=1024, N=512.
// Tile 128x128x8, 256 threads, 8x8 microtile with split-quadrant mapping:
// rows {ty*4..+3, 64+ty*4..+3}, cols {tx*4..+3, 64+tx*4..+3} -> conflict-free
// float4 shared loads.
// ---------------------------------------------------------------------------
__global__ __launch_bounds__(256, 2) void gemm1_kernel(
    const float* __restrict__ x, const float* __restrict__ Wf,
    const float* __restrict__ bf)
{
    __shared__ float As[8][128];   // [k][m]
    __shared__ float Bs[8][128];   // [k][n]

    const int tid = threadIdx.x;
    const int m0  = blockIdx.y * 128;
    const int n0  = blockIdx.x * 128;
    const int tx  = tid & 15;
    const int ty  = tid >> 4;

    // A-tile load mapping: 128 rows x 8 k = 1024 floats, float4 each
    const int arow = tid >> 1;
    const int akq  = (tid & 1) * 4;
    // B-tile load mapping: 8 k-rows x 128 n = 1024 floats, float4 each
    const int bkr  = tid >> 5;          // 0..7
    const int bn4  = (tid & 31) * 4;    // 0..124

    float acc[8][8];
#pragma unroll
    for (int i = 0; i < 8; i++)
#pragma unroll
        for (int j = 0; j < 8; j++) acc[i][j] = 0.f;

    const float* xA = x  + (size_t)(m0 + arow) * DIN + akq;
    const float* wB = Wf + (size_t)bkr * LDIM + n0 + bn4;

    for (int kt = 0; kt < DIN / 8; kt++) {
        float4 av = *(const float4*)(xA + kt * 8);
        float4 bv = *(const float4*)(wB + (size_t)kt * 8 * LDIM);
        As[akq + 0][arow] = av.x;
        As[akq + 1][arow] = av.y;
        As[akq + 2][arow] = av.z;
        As[akq + 3][arow] = av.w;
        *(float4*)&Bs[bkr][bn4] = bv;
        __syncthreads();
#pragma unroll
        for (int k = 0; k < 8; k++) {
            float4 a0 = *(const float4*)&As[k][ty * 4];
            float4 a1 = *(const float4*)&As[k][64 + ty * 4];
            float4 b0 = *(const float4*)&Bs[k][tx * 4];
            float4 b1 = *(const float4*)&Bs[k][64 + tx * 4];
            float ra[8] = {a0.x, a0.y, a0.z, a0.w, a1.x, a1.y, a1.z, a1.w};
            float rb[8] = {b0.x, b0.y, b0.z, b0.w, b1.x, b1.y, b1.z, b1.w};
#pragma unroll
            for (int i = 0; i < 8; i++)
#pragma unroll
                for (int j = 0; j < 8; j++)
                    acc[i][j] = fmaf(ra[i], rb[j], acc[i][j]);
        }
        __syncthreads();
    }

    // Epilogue: + bias, relu, store float4s
#pragma unroll
    for (int i = 0; i < 8; i++) {
        const int m = m0 + ((i < 4) ? (ty * 4 + i) : (64 + ty * 4 + i - 4));
#pragma unroll
        for (int jg = 0; jg < 2; jg++) {
            const int n = n0 + jg * 64 + tx * 4;
            float4 v;
            v.x = fmaxf(acc[i][jg * 4 + 0] + bf[n + 0], 0.f);
            v.y = fmaxf(acc[i][jg * 4 + 1] + bf[n + 1], 0.f);
            v.z = fmaxf(acc[i][jg * 4 + 2] + bf[n + 2], 0.f);
            v.w = fmaxf(acc[i][jg * 4 + 3] + bf[n + 3], 0.f);
            *(float4*)&g_h[(size_t)m * LDIM + n] = v;
        }
    }
}

// ---------------------------------------------------------------------------
// GEMM2 (fused): for each row n, each D-tile of 64 cols:
//   spart = sum_d tanh(h@Wa+ba)_d * sigmoid(h@Wb+bb)_d * wc_d
// Tile 128(M) x 64(D) x 16(K), 256 threads, dual accumulators 8x4.
// In-block reduce over the 64 D-cols -> g_spart[dtile][row].
// ---------------------------------------------------------------------------
__global__ __launch_bounds__(256, 2) void gemm2_kernel(
    const float* __restrict__ Wa, const float* __restrict__ ba,
    const float* __restrict__ Wb, const float* __restrict__ bb,
    const float* __restrict__ Wc)
{
    __shared__ float Hs[16][128];   // [k][m]
    __shared__ float Was[16][64];   // [k][d]
    __shared__ float Wbs[16][64];
    __shared__ float red[128][17];  // row-sum reduction, padded

    const int tid = threadIdx.x;
    const int m0  = blockIdx.y * 128;
    const int n0  = blockIdx.x * 64;
    const int tx  = tid & 15;
    const int ty  = tid >> 4;

    const int hrow = tid >> 1;
    const int hkq  = (tid & 1) * 8;
    const int wkr  = tid >> 4;          // 0..15
    const int wn4  = (tid & 15) * 4;    // 0..60

    float acca[8][4], accg[8][4];
#pragma unroll
    for (int i = 0; i < 8; i++)
#pragma unroll
        for (int j = 0; j < 4; j++) { acca[i][j] = 0.f; accg[i][j] = 0.f; }

    const float* hA = g_h + (size_t)(m0 + hrow) * LDIM + hkq;
    const float* wa = Wa + (size_t)wkr * DDIM + n0 + wn4;
    const float* wb = Wb + (size_t)wkr * DDIM + n0 + wn4;

    for (int kt = 0; kt < LDIM / 16; kt++) {
        float4 h0 = *(const float4*)(hA + kt * 16);
        float4 h1 = *(const float4*)(hA + kt * 16 + 4);
        float4 uav = *(const float4*)(wa + (size_t)kt * 16 * DDIM);
        float4 ubv = *(const float4*)(wb + (size_t)kt * 16 * DDIM);
        Hs[hkq + 0][hrow] = h0.x;
        Hs[hkq + 1][hrow] = h0.y;
        Hs[hkq + 2][hrow] = h0.z;
        Hs[hkq + 3][hrow] = h0.w;
        Hs[hkq + 4][hrow] = h1.x;
        Hs[hkq + 5][hrow] = h1.y;
        Hs[hkq + 6][hrow] = h1.z;
        Hs[hkq + 7][hrow] = h1.w;
        *(float4*)&Was[wkr][wn4] = uav;
        *(float4*)&Wbs[wkr][wn4] = ubv;
        __syncthreads();
#pragma unroll
        for (int k = 0; k < 16; k++) {
            float4 a0 = *(const float4*)&Hs[k][ty * 4];
            float4 a1 = *(const float4*)&Hs[k][64 + ty * 4];
            float4 u  = *(const float4*)&Was[k][tx * 4];
            float4 v  = *(const float4*)&Wbs[k][tx * 4];
            float ra[8] = {a0.x, a0.y, a0.z, a0.w, a1.x, a1.y, a1.z, a1.w};
            float ru[4] = {u.x, u.y, u.z, u.w};
            float rv[4] = {v.x, v.y, v.z, v.w};
#pragma unroll
            for (int i = 0; i < 8; i++)
#pragma unroll
                for (int j = 0; j < 4; j++) {
                    acca[i][j] = fmaf(ra[i], ru[j], acca[i][j]);
                    accg[i][j] = fmaf(ra[i], rv[j], accg[i][j]);
                }
        }
        __syncthreads();
    }

    // Epilogue: tanh * sigmoid * wc, sum over this thread's 4 cols
    float ban[4], bbn[4], wcn[4];
#pragma unroll
    for (int j = 0; j < 4; j++) {
        const int n = n0 + tx * 4 + j;
        ban[j] = ba[n]; bbn[j] = bb[n]; wcn[j] = Wc[n];
    }
    float rs[8];
#pragma unroll
    for (int i = 0; i < 8; i++) {
        float s = 0.f;
#pragma unroll
        for (int j = 0; j < 4; j++) {
            float aa = tanhf(acca[i][j] + ban[j]);
            float gg = 1.f / (1.f + expf(-(accg[i][j] + bbn[j])));
            s += aa * gg * wcn[j];
        }
        rs[i] = s;
    }
#pragma unroll
    for (int i = 0; i < 8; i++) {
        const int r = (i < 4) ? (ty * 4 + i) : (64 + ty * 4 + i - 4);
        red[r][tx] = rs[i];
    }
    __syncthreads();
    if (tid < 128) {
        float t = 0.f;
#pragma unroll
        for (int c = 0; c < 16; c++) t += red[tid][c];
        g_spart[(size_t)blockIdx.x * MTOT + m0 + tid] = t;
    }
}

// ---------------------------------------------------------------------------
// Assemble s = bc + sum of D-tile partials; per-block max
// ---------------------------------------------------------------------------
__global__ void sred_kernel(const float* __restrict__ bc)
{
    __shared__ float sm[256];
    const int b = blockIdx.y, tid = threadIdx.x;
    const int n = blockIdx.x * 256 + tid;
    float v = -3.4e38f;
    if (n < NPB) {
        const int gm = b * NPB + n;
        float s = bc[0];
#pragma unroll
        for (int t = 0; t < NDT; t++) s += g_spart[(size_t)t * MTOT + gm];
        g_s[gm] = s;
        v = s;
    }
    sm[tid] = v;
    __syncthreads();
    for (int o = 128; o > 0; o >>= 1) {
        if (tid < o) sm[tid] = fmaxf(sm[tid], sm[tid + o]);
        __syncthreads();
    }
    if (tid == 0) g_bmax[b * NCHUNK + blockIdx.x] = sm[0];
}

__global__ void maxfin_kernel()
{
    __shared__ float sm[256];
    const int b = blockIdx.x, tid = threadIdx.x;
    sm[tid] = (tid < NCHUNK) ? g_bmax[b * NCHUNK + tid] : -3.4e38f;
    __syncthreads();
    for (int o = 128; o > 0; o >>= 1) {
        if (tid < o) sm[tid] = fmaxf(sm[tid], sm[tid + o]);
        __syncthreads();
    }
    if (tid == 0) g_maxv[b] = sm[0];
}

// ---------------------------------------------------------------------------
// Weighted pool partials: Upart[l] = sum_{n in chunk} exp(s-m) * h[n][l]
// ---------------------------------------------------------------------------
__global__ __launch_bounds__(256) void pool_kernel()
{
    __shared__ float esh[256];
    __shared__ float zr[256];
    const int b = blockIdx.y, cx = blockIdx.x, tid = threadIdx.x;
    const int base = cx * 256;
    const int n = base + tid;
    float e = 0.f;
    if (n < NPB) e = expf(g_s[b * NPB + n] - g_maxv[b]);
    esh[tid] = e;
    zr[tid]  = e;
    __syncthreads();
    for (int o = 128; o > 0; o >>= 1) {
        if (tid < o) zr[tid] += zr[tid + o];
        __syncthreads();
    }
    if (tid == 0) g_Zpart[b * NCHUNK + cx] = zr[0];

    const int rmax = min(256, NPB - base);
    const int c = tid * 2;
    const float* hb = g_h + ((size_t)b * NPB + base) * LDIM + c;
    float ax = 0.f, ay = 0.f;
    for (int r = 0; r < rmax; r++) {
        const float w = esh[r];
        float2 hv = *(const float2*)(hb + (size_t)r * LDIM);
        ax = fmaf(w, hv.x, ax);
        ay = fmaf(w, hv.y, ay);
    }
    float* up = g_Upart + (size_t)(b * NCHUNK + cx) * LDIM + c;
    up[0] = ax;
    up[1] = ay;
}

// ---------------------------------------------------------------------------
// Final: reduce partials, divide by Z, classifier matvec -> out [2,2]
// ---------------------------------------------------------------------------
__global__ void final_kernel(const float* __restrict__ Wcls,
                             const float* __restrict__ bcls,
                             float* __restrict__ out)
{
    __shared__ float r0[512], r1[512];
    const int b = blockIdx.x, l = threadIdx.x;
    float U = 0.f;
    for (int c = 0; c < NCHUNK; c++)
        U += g_Upart[(size_t)(b * NCHUNK + c) * LDIM + l];
    float Z = 0.f;
    for (int c = 0; c < NCHUNK; c++) Z += g_Zpart[b * NCHUNK + c];
    const float p = U / Z;
    r0[l] = p * Wcls[l * 2 + 0];
    r1[l] = p * Wcls[l * 2 + 1];
    __syncthreads();
    for (int o = 256; o > 0; o >>= 1) {
        if (l < o) { r0[l] += r0[l + o]; r1[l] += r1[l + o]; }
        __syncthreads();
    }
    if (l == 0) {
        out[b * 2 + 0] = r0[0] + bcls[0];
        out[b * 2 + 1] = r1[0] + bcls[1];
    }
}

// ---------------------------------------------------------------------------
extern "C" void kernel_launch(void* const* d_in, const int* in_sizes, int n_in,
                              void* d_out, int out_size)
{
    const float* x    = (const float*)d_in[0];
    const float* Wf   = (const float*)d_in[1];
    const float* bf   = (const float*)d_in[2];
    const float* Wa   = (const float*)d_in[3];
    const float* ba   = (const float*)d_in[4];
    const float* Wb   = (const float*)d_in[5];
    const float* bb   = (const float*)d_in[6];
    const float* Wc   = (const float*)d_in[7];
    const float* bc   = (const float*)d_in[8];
    const float* Wcls = (const float*)d_in[9];
    const float* bcls = (const float*)d_in[10];
    float* out = (float*)d_out;

    dim3 g1(LDIM / 128, MTOT / 128);      // (4, 625)
    gemm1_kernel<<<g1, 256>>>(x, Wf, bf);

    dim3 g2(DDIM / 64, MTOT / 128);       // (6, 625)
    gemm2_kernel<<<g2, 256>>>(Wa, ba, Wb, bb, Wc);

    dim3 g3(NCHUNK, NBATCH);
    sred_kernel<<<g3, 256>>>(bc);
    maxfin_kernel<<<NBATCH, 256>>>();
    pool_kernel<<<g3, 256>>>();
    final_kernel<<<NBATCH, 512>>>(Wcls, bcls, out);
}

// round 3
// speedup vs baseline: 2.9832x; 2.9832x over previous
#include <cuda_runtime.h>
#include <math.h>
#include <stdint.h>

// Problem constants
#define MTOT   80000
#define NBATCH 2
#define NPB    40000
#define DIN    1024
#define LDIM   512
#define DDIM   384
#define NDT    6          // six 64-wide d-tiles in gemm2
#define NCHUNK 157        // ceil(40000/256)

// Scratch (device globals)
__device__ __align__(16) float g_xt[(size_t)MTOT * DIN];     // x in tf32 (rna)
__device__ __align__(16) float g_h[(size_t)MTOT * LDIM];     // relu(x@Wf+bf), tf32-rounded
__device__ __align__(16) float g_Wtf[DIN * LDIM];            // Wf tf32 (same layout)
__device__ __align__(16) float g_Wta[LDIM * DDIM];           // Wa tf32
__device__ __align__(16) float g_Wtb[LDIM * DDIM];           // Wb tf32
__device__ float g_spart[(size_t)NDT * MTOT];
__device__ float g_s[MTOT];
__device__ float g_bmax[NBATCH * NCHUNK];
__device__ float g_maxv[NBATCH];
__device__ __align__(16) float g_Upart[(size_t)NBATCH * NCHUNK * LDIM];
__device__ float g_Zpart[NBATCH * NCHUNK];

// ---------------------------------------------------------------------------
// Helpers
// ---------------------------------------------------------------------------
__device__ __forceinline__ uint32_t smem_u32(const void* p) {
    uint32_t a;
    asm("{ .reg .u64 t; cvta.to.shared.u64 t, %1; cvt.u32.u64 %0, t; }"
        : "=r"(a) : "l"(p));
    return a;
}
__device__ __forceinline__ float to_tf32f(float x) {
    uint32_t u;
    asm("cvt.rna.tf32.f32 %0, %1;" : "=r"(u) : "f"(x));
    return __uint_as_float(u);
}
__device__ __forceinline__ void cp16(uint32_t dst, const void* src) {
    asm volatile("cp.async.cg.shared.global [%0], [%1], 16;" :: "r"(dst), "l"(src));
}
#define CP_COMMIT() asm volatile("cp.async.commit_group;")
#define CP_WAIT1()  asm volatile("cp.async.wait_group 1;")

__device__ __forceinline__ void mma8(float& c0, float& c1, float& c2, float& c3,
                                     uint32_t a0, uint32_t a1, uint32_t a2, uint32_t a3,
                                     uint32_t b0, uint32_t b1) {
    asm volatile(
        "mma.sync.aligned.m16n8k8.row.col.f32.tf32.tf32.f32 "
        "{%0,%1,%2,%3},{%4,%5,%6,%7},{%8,%9},{%0,%1,%2,%3};"
        : "+f"(c0), "+f"(c1), "+f"(c2), "+f"(c3)
        : "r"(a0), "r"(a1), "r"(a2), "r"(a3), "r"(b0), "r"(b1));
}

// ---------------------------------------------------------------------------
// Pre-passes: tf32(rna) copies
// ---------------------------------------------------------------------------
__global__ void prep_x(const float* __restrict__ x)
{
    const size_t tot = (size_t)MTOT * DIN / 4;
    size_t i = (size_t)blockIdx.x * 256 + threadIdx.x;
    const size_t step = (size_t)gridDim.x * 256;
    for (; i < tot; i += step) {
        float4 v = ((const float4*)x)[i];
        v.x = to_tf32f(v.x); v.y = to_tf32f(v.y);
        v.z = to_tf32f(v.z); v.w = to_tf32f(v.w);
        ((float4*)g_xt)[i] = v;
    }
}

__global__ void prep_w(const float* __restrict__ Wf,
                       const float* __restrict__ Wa,
                       const float* __restrict__ Wb)
{
    int idx = blockIdx.x * 256 + threadIdx.x;
    if (idx < DIN * LDIM) g_Wtf[idx] = to_tf32f(Wf[idx]);
    if (idx < LDIM * DDIM) {
        g_Wta[idx] = to_tf32f(Wa[idx]);
        g_Wtb[idx] = to_tf32f(Wb[idx]);
    }
}

// ---------------------------------------------------------------------------
// GEMM1 (mma.sync tf32): h = relu(x @ Wf + bf), M=80000 K=1024 N=512.
// CTA 128x128x32, 3-stage cp.async, 8 warps (2m x 4n), warp tile 64x32.
// smem A [128][36] (stride 36 w), B [32][136] -> conflict-free frag loads.
// ---------------------------------------------------------------------------
#define G1_BOFF  18432
#define G1_STAGE 35840
#define G1_SMEM  (3 * G1_STAGE)

__global__ void __launch_bounds__(256, 2) gemm1_mma(const float* __restrict__ bfp)
{
    extern __shared__ char smch[];
    const uint32_t sb = smem_u32(smch);
    const int tid  = threadIdx.x;
    const int warp = tid >> 5, lane = tid & 31;
    const int gr = lane >> 2, tg = lane & 3;
    const int n0 = blockIdx.x * 128;
    const int m0 = blockIdx.y * 128;
    const int wm = (warp >> 2) * 64, wn = (warp & 3) * 32;

    auto issue = [&](int ks, int st) {
        const uint32_t base = sb + st * G1_STAGE;
#pragma unroll
        for (int i = 0; i < 4; i++) {
            int idx = tid + i * 256;
            int row = idx >> 3, c4 = idx & 7;
            cp16(base + row * 144 + c4 * 16,
                 g_xt + (size_t)(m0 + row) * DIN + ks * 32 + c4 * 4);
        }
#pragma unroll
        for (int i = 0; i < 4; i++) {
            int idx = tid + i * 256;
            int kr = idx >> 5, nc = idx & 31;
            cp16(base + G1_BOFF + kr * 544 + nc * 16,
                 g_Wtf + (size_t)(ks * 32 + kr) * LDIM + n0 + nc * 4);
        }
    };

    float acc[4][4][4];
#pragma unroll
    for (int a = 0; a < 4; a++)
#pragma unroll
        for (int b = 0; b < 4; b++)
#pragma unroll
            for (int c = 0; c < 4; c++) acc[a][b][c] = 0.f;

    issue(0, 0); CP_COMMIT();
    issue(1, 1); CP_COMMIT();

    for (int ks = 0; ks < 32; ks++) {
        CP_WAIT1();
        __syncthreads();
        if (ks + 2 < 32) issue(ks + 2, (ks + 2) % 3);
        CP_COMMIT();
        const uint32_t* A = (const uint32_t*)(smch + (ks % 3) * G1_STAGE);
        const uint32_t* B = (const uint32_t*)(smch + (ks % 3) * G1_STAGE + G1_BOFF);
#pragma unroll
        for (int kk = 0; kk < 4; kk++) {
            const int kb = kk * 8;
            uint32_t af[4][4];
#pragma unroll
            for (int mf = 0; mf < 4; mf++) {
                const int m = wm + mf * 16 + gr;
                af[mf][0] = A[m * 36 + kb + tg];
                af[mf][1] = A[(m + 8) * 36 + kb + tg];
                af[mf][2] = A[m * 36 + kb + tg + 4];
                af[mf][3] = A[(m + 8) * 36 + kb + tg + 4];
            }
            uint32_t bfr[4][2];
#pragma unroll
            for (int nf = 0; nf < 4; nf++) {
                const int n = wn + nf * 8 + gr;
                bfr[nf][0] = B[(kb + tg) * 136 + n];
                bfr[nf][1] = B[(kb + tg + 4) * 136 + n];
            }
#pragma unroll
            for (int mf = 0; mf < 4; mf++)
#pragma unroll
                for (int nf = 0; nf < 4; nf++)
                    mma8(acc[mf][nf][0], acc[mf][nf][1], acc[mf][nf][2], acc[mf][nf][3],
                         af[mf][0], af[mf][1], af[mf][2], af[mf][3],
                         bfr[nf][0], bfr[nf][1]);
        }
    }

    // Epilogue: bias + relu, round to tf32 (rna) so gemm2 A-operand is clean
#pragma unroll
    for (int mf = 0; mf < 4; mf++) {
        const int r0 = m0 + wm + mf * 16 + gr;
#pragma unroll
        for (int nf = 0; nf < 4; nf++) {
            const int n = n0 + wn + nf * 8 + 2 * tg;
            const float b0v = bfp[n], b1v = bfp[n + 1];
            float2 v0, v1;
            v0.x = to_tf32f(fmaxf(acc[mf][nf][0] + b0v, 0.f));
            v0.y = to_tf32f(fmaxf(acc[mf][nf][1] + b1v, 0.f));
            v1.x = to_tf32f(fmaxf(acc[mf][nf][2] + b0v, 0.f));
            v1.y = to_tf32f(fmaxf(acc[mf][nf][3] + b1v, 0.f));
            *(float2*)&g_h[(size_t)r0 * LDIM + n] = v0;
            *(float2*)&g_h[(size_t)(r0 + 8) * LDIM + n] = v1;
        }
    }
}

// ---------------------------------------------------------------------------
// GEMM2 (mma.sync tf32, fused): per (d-tile of 64, m-tile of 128):
//   acca = h @ Wa[:,dtile], accg = h @ Wb[:,dtile]   (K=512)
//   spart[row] = sum_d tanh(acca+ba)*sigmoid(accg+bb)*wc
// 8 warps (4m x 2n), warp tile 32x32, dual accumulators, A-frags shared.
// ---------------------------------------------------------------------------
#define G2_BAOFF 18432
#define G2_BBOFF 27648
#define G2_STAGE 36864
#define G2_SMEM  (3 * G2_STAGE)

__global__ void __launch_bounds__(256, 2) gemm2_mma(
    const float* __restrict__ ba, const float* __restrict__ bb,
    const float* __restrict__ Wc)
{
    extern __shared__ char smch[];
    __shared__ float red[256];
    const uint32_t sb = smem_u32(smch);
    const int tid  = threadIdx.x;
    const int warp = tid >> 5, lane = tid & 31;
    const int gr = lane >> 2, tg = lane & 3;
    const int n0 = blockIdx.x * 64;
    const int m0 = blockIdx.y * 128;
    const int wm = (warp >> 1) * 32, wn = (warp & 1) * 32;

    auto issue = [&](int ks, int st) {
        const uint32_t base = sb + st * G2_STAGE;
#pragma unroll
        for (int i = 0; i < 4; i++) {
            int idx = tid + i * 256;
            int row = idx >> 3, c4 = idx & 7;
            cp16(base + row * 144 + c4 * 16,
                 g_h + (size_t)(m0 + row) * LDIM + ks * 32 + c4 * 4);
        }
#pragma unroll
        for (int i = 0; i < 2; i++) {
            int idx = tid + i * 256;
            int kr = idx >> 4, nc = idx & 15;
            cp16(base + G2_BAOFF + kr * 288 + nc * 16,
                 g_Wta + (size_t)(ks * 32 + kr) * DDIM + n0 + nc * 4);
            cp16(base + G2_BBOFF + kr * 288 + nc * 16,
                 g_Wtb + (size_t)(ks * 32 + kr) * DDIM + n0 + nc * 4);
        }
    };

    float acca[2][4][4], accg[2][4][4];
#pragma unroll
    for (int a = 0; a < 2; a++)
#pragma unroll
        for (int b = 0; b < 4; b++)
#pragma unroll
            for (int c = 0; c < 4; c++) { acca[a][b][c] = 0.f; accg[a][b][c] = 0.f; }

    issue(0, 0); CP_COMMIT();
    issue(1, 1); CP_COMMIT();

    for (int ks = 0; ks < 16; ks++) {
        CP_WAIT1();
        __syncthreads();
        if (ks + 2 < 16) issue(ks + 2, (ks + 2) % 3);
        CP_COMMIT();
        const uint32_t* A  = (const uint32_t*)(smch + (ks % 3) * G2_STAGE);
        const uint32_t* Ba = (const uint32_t*)(smch + (ks % 3) * G2_STAGE + G2_BAOFF);
        const uint32_t* Bb = (const uint32_t*)(smch + (ks % 3) * G2_STAGE + G2_BBOFF);
#pragma unroll
        for (int kk = 0; kk < 4; kk++) {
            const int kb = kk * 8;
            uint32_t af[2][4];
#pragma unroll
            for (int mf = 0; mf < 2; mf++) {
                const int m = wm + mf * 16 + gr;
                af[mf][0] = A[m * 36 + kb + tg];
                af[mf][1] = A[(m + 8) * 36 + kb + tg];
                af[mf][2] = A[m * 36 + kb + tg + 4];
                af[mf][3] = A[(m + 8) * 36 + kb + tg + 4];
            }
            uint32_t bafr[4][2], bbfr[4][2];
#pragma unroll
            for (int nf = 0; nf < 4; nf++) {
                const int n = wn + nf * 8 + gr;
                bafr[nf][0] = Ba[(kb + tg) * 72 + n];
                bafr[nf][1] = Ba[(kb + tg + 4) * 72 + n];
                bbfr[nf][0] = Bb[(kb + tg) * 72 + n];
                bbfr[nf][1] = Bb[(kb + tg + 4) * 72 + n];
            }
#pragma unroll
            for (int mf = 0; mf < 2; mf++)
#pragma unroll
                for (int nf = 0; nf < 4; nf++) {
                    mma8(acca[mf][nf][0], acca[mf][nf][1], acca[mf][nf][2], acca[mf][nf][3],
                         af[mf][0], af[mf][1], af[mf][2], af[mf][3],
                         bafr[nf][0], bafr[nf][1]);
                    mma8(accg[mf][nf][0], accg[mf][nf][1], accg[mf][nf][2], accg[mf][nf][3],
                         af[mf][0], af[mf][1], af[mf][2], af[mf][3],
                         bbfr[nf][0], bbfr[nf][1]);
                }
        }
    }

    // Epilogue: tanh * sigmoid * wc, reduce over 64 d-cols per row
    float bav[4][2], bbv[4][2], wcv[4][2];
#pragma unroll
    for (int nf = 0; nf < 4; nf++) {
        const int d = n0 + wn + nf * 8 + 2 * tg;
        bav[nf][0] = ba[d]; bav[nf][1] = ba[d + 1];
        bbv[nf][0] = bb[d]; bbv[nf][1] = bb[d + 1];
        wcv[nf][0] = Wc[d]; wcv[nf][1] = Wc[d + 1];
    }
#pragma unroll
    for (int mf = 0; mf < 2; mf++) {
#pragma unroll
        for (int h = 0; h < 2; h++) {
            float s = 0.f;
#pragma unroll
            for (int nf = 0; nf < 4; nf++) {
#pragma unroll
                for (int c = 0; c < 2; c++) {
                    const float av = tanhf(acca[mf][nf][h * 2 + c] + bav[nf][c]);
                    const float gv = 1.f / (1.f + expf(-(accg[mf][nf][h * 2 + c] + bbv[nf][c])));
                    s = fmaf(av * gv, wcv[nf][c], s);
                }
            }
            s += __shfl_xor_sync(0xFFFFFFFF, s, 1);
            s += __shfl_xor_sync(0xFFFFFFFF, s, 2);
            if (tg == 0)
                red[(wm + mf * 16 + h * 8 + gr) * 2 + (warp & 1)] = s;
        }
    }
    __syncthreads();
    if (tid < 128)
        g_spart[(size_t)blockIdx.x * MTOT + m0 + tid] = red[tid * 2] + red[tid * 2 + 1];
}

// ---------------------------------------------------------------------------
// s = bc + sum of d-tile partials; per-block max
// ---------------------------------------------------------------------------
__global__ void sred_kernel(const float* __restrict__ bc)
{
    __shared__ float sm[256];
    const int b = blockIdx.y, tid = threadIdx.x;
    const int n = blockIdx.x * 256 + tid;
    float v = -3.4e38f;
    if (n < NPB) {
        const int gm = b * NPB + n;
        float s = bc[0];
#pragma unroll
        for (int t = 0; t < NDT; t++) s += g_spart[(size_t)t * MTOT + gm];
        g_s[gm] = s;
        v = s;
    }
    sm[tid] = v;
    __syncthreads();
    for (int o = 128; o > 0; o >>= 1) {
        if (tid < o) sm[tid] = fmaxf(sm[tid], sm[tid + o]);
        __syncthreads();
    }
    if (tid == 0) g_bmax[b * NCHUNK + blockIdx.x] = sm[0];
}

__global__ void maxfin_kernel()
{
    __shared__ float sm[256];
    const int b = blockIdx.x, tid = threadIdx.x;
    sm[tid] = (tid < NCHUNK) ? g_bmax[b * NCHUNK + tid] : -3.4e38f;
    __syncthreads();
    for (int o = 128; o > 0; o >>= 1) {
        if (tid < o) sm[tid] = fmaxf(sm[tid], sm[tid + o]);
        __syncthreads();
    }
    if (tid == 0) g_maxv[b] = sm[0];
}

// ---------------------------------------------------------------------------
// Weighted pool partials
// ---------------------------------------------------------------------------
__global__ void __launch_bounds__(256) pool_kernel()
{
    __shared__ float esh[256];
    __shared__ float zr[256];
    const int b = blockIdx.y, cx = blockIdx.x, tid = threadIdx.x;
    const int base = cx * 256;
    const int n = base + tid;
    float e = 0.f;
    if (n < NPB) e = expf(g_s[b * NPB + n] - g_maxv[b]);
    esh[tid] = e;
    zr[tid]  = e;
    __syncthreads();
    for (int o = 128; o > 0; o >>= 1) {
        if (tid < o) zr[tid] += zr[tid + o];
        __syncthreads();
    }
    if (tid == 0) g_Zpart[b * NCHUNK + cx] = zr[0];

    const int rmax = min(256, NPB - base);
    const int c = tid * 2;
    const float* hb = g_h + ((size_t)b * NPB + base) * LDIM + c;
    float ax = 0.f, ay = 0.f;
    for (int r = 0; r < rmax; r++) {
        const float w = esh[r];
        float2 hv = *(const float2*)(hb + (size_t)r * LDIM);
        ax = fmaf(w, hv.x, ax);
        ay = fmaf(w, hv.y, ay);
    }
    float* up = g_Upart + (size_t)(b * NCHUNK + cx) * LDIM + c;
    up[0] = ax;
    up[1] = ay;
}

// ---------------------------------------------------------------------------
// Final reduce + classifier
// ---------------------------------------------------------------------------
__global__ void final_kernel(const float* __restrict__ Wcls,
                             const float* __restrict__ bcls,
                             float* __restrict__ out)
{
    __shared__ float r0[512], r1[512];
    const int b = blockIdx.x, l = threadIdx.x;
    float U = 0.f;
    for (int c = 0; c < NCHUNK; c++)
        U += g_Upart[(size_t)(b * NCHUNK + c) * LDIM + l];
    float Z = 0.f;
    for (int c = 0; c < NCHUNK; c++) Z += g_Zpart[b * NCHUNK + c];
    const float p = U / Z;
    r0[l] = p * Wcls[l * 2 + 0];
    r1[l] = p * Wcls[l * 2 + 1];
    __syncthreads();
    for (int o = 256; o > 0; o >>= 1) {
        if (l < o) { r0[l] += r0[l + o]; r1[l] += r1[l + o]; }
        __syncthreads();
    }
    if (l == 0) {
        out[b * 2 + 0] = r0[0] + bcls[0];
        out[b * 2 + 1] = r1[0] + bcls[1];
    }
}

// ---------------------------------------------------------------------------
extern "C" void kernel_launch(void* const* d_in, const int* in_sizes, int n_in,
                              void* d_out, int out_size)
{
    const float* x    = (const float*)d_in[0];
    const float* Wf   = (const float*)d_in[1];
    const float* bf   = (const float*)d_in[2];
    const float* Wa   = (const float*)d_in[3];
    const float* ba   = (const float*)d_in[4];
    const float* Wb   = (const float*)d_in[5];
    const float* bb   = (const float*)d_in[6];
    const float* Wc   = (const float*)d_in[7];
    const float* bc   = (const float*)d_in[8];
    const float* Wcls = (const float*)d_in[9];
    const float* bcls = (const float*)d_in[10];
    float* out = (float*)d_out;

    cudaFuncSetAttribute(gemm1_mma, cudaFuncAttributeMaxDynamicSharedMemorySize, G1_SMEM);
    cudaFuncSetAttribute(gemm2_mma, cudaFuncAttributeMaxDynamicSharedMemorySize, G2_SMEM);

    prep_x<<<20000, 256>>>(x);
    prep_w<<<2048, 256>>>(Wf, Wa, Wb);

    dim3 g1(LDIM / 128, MTOT / 128);      // (4, 625)
    gemm1_mma<<<g1, 256, G1_SMEM>>>(bf);

    dim3 g2(DDIM / 64, MTOT / 128);       // (6, 625)
    gemm2_mma<<<g2, 256, G2_SMEM>>>(ba, bb, Wc);

    dim3 g3(NCHUNK, NBATCH);
    sred_kernel<<<g3, 256>>>(bc);
    maxfin_kernel<<<NBATCH, 256>>>();
    pool_kernel<<<g3, 256>>>();
    final_kernel<<<NBATCH, 512>>>(Wcls, bcls, out);
}

// round 6
// speedup vs baseline: 3.3231x; 1.1139x over previous
#include <cuda_runtime.h>
#include <math.h>
#include <stdint.h>

// Problem constants
#define MTOT   80000
#define NBATCH 2
#define NPB    40000
#define DIN    1024
#define LDIM   512
#define DDIM   384
#define NDT    6
#define NCHUNK 157

// Scratch (device globals)
__device__ __align__(16) float g_h[(size_t)MTOT * LDIM];   // relu(x@Wf+bf), fp32
__device__ __align__(16) float g_Wtf[LDIM * DIN];          // Wf^T [n][k] tf32
__device__ __align__(16) float g_Wta[DDIM * LDIM];         // Wa^T [d][k] tf32
__device__ __align__(16) float g_Wtb[DDIM * LDIM];         // Wb^T [d][k] tf32
__device__ float g_spart[(size_t)NDT * MTOT];
__device__ float g_s[MTOT];
__device__ float g_bmax[NBATCH * NCHUNK];
__device__ float g_maxv[NBATCH];
__device__ __align__(16) float g_Upart[(size_t)NBATCH * NCHUNK * LDIM];
__device__ float g_Zpart[NBATCH * NCHUNK];

// ---------------------------------------------------------------------------
// Helpers
// ---------------------------------------------------------------------------
__device__ __forceinline__ uint32_t smem_u32(const void* p) {
    uint32_t a;
    asm("{ .reg .u64 t; cvta.to.shared.u64 t, %1; cvt.u32.u64 %0, t; }"
        : "=r"(a) : "l"(p));
    return a;
}
__device__ __forceinline__ float to_tf32f(float x) {
    uint32_t u;
    asm("cvt.rna.tf32.f32 %0, %1;" : "=r"(u) : "f"(x));
    return __uint_as_float(u);
}
__device__ __forceinline__ void cp16(uint32_t dst, const void* src) {
    asm volatile("cp.async.cg.shared.global [%0], [%1], 16;" :: "r"(dst), "l"(src));
}
#define CP_COMMIT() asm volatile("cp.async.commit_group;")
#define CP_WAIT1()  asm volatile("cp.async.wait_group 1;")

__device__ __forceinline__ void ldsm4(uint32_t& r0, uint32_t& r1, uint32_t& r2,
                                      uint32_t& r3, uint32_t addr) {
    asm volatile("ldmatrix.sync.aligned.m8n8.x4.shared.b16 {%0,%1,%2,%3}, [%4];"
                 : "=r"(r0), "=r"(r1), "=r"(r2), "=r"(r3) : "r"(addr));
}
__device__ __forceinline__ void ldsm2(uint32_t& r0, uint32_t& r1, uint32_t addr) {
    asm volatile("ldmatrix.sync.aligned.m8n8.x2.shared.b16 {%0,%1}, [%2];"
                 : "=r"(r0), "=r"(r1) : "r"(addr));
}
__device__ __forceinline__ void mma8(float& c0, float& c1, float& c2, float& c3,
                                     uint32_t a0, uint32_t a1, uint32_t a2, uint32_t a3,
                                     uint32_t b0, uint32_t b1) {
    asm volatile(
        "mma.sync.aligned.m16n8k8.row.col.f32.tf32.tf32.f32 "
        "{%0,%1,%2,%3},{%4,%5,%6,%7},{%8,%9},{%0,%1,%2,%3};"
        : "+f"(c0), "+f"(c1), "+f"(c2), "+f"(c3)
        : "r"(a0), "r"(a1), "r"(a2), "r"(a3), "r"(b0), "r"(b1));
}

// ---------------------------------------------------------------------------
// Weight prep: transpose to K-major [n][k] + tf32(rna)
// ---------------------------------------------------------------------------
__global__ void prep_w(const float* __restrict__ Wf,
                       const float* __restrict__ Wa,
                       const float* __restrict__ Wb)
{
    int idx = blockIdx.x * 256 + threadIdx.x;
    if (idx < LDIM * DIN) {
        int n = idx >> 10, k = idx & 1023;
        g_Wtf[idx] = to_tf32f(Wf[k * LDIM + n]);
    }
    if (idx < DDIM * LDIM) {
        int d = idx >> 9, k = idx & 511;
        g_Wta[idx] = to_tf32f(Wa[k * DDIM + d]);
        g_Wtb[idx] = to_tf32f(Wb[k * DDIM + d]);
    }
}

// ---------------------------------------------------------------------------
// GEMM1: h = relu(x @ Wf + bf). CTA 128x128x32, 3-stage cp.async, 8 warps
// (2m x 4n), warp tile 64x32. A [128][36w], B(K-major) [128][36w], ldmatrix.
// ---------------------------------------------------------------------------
#define G1_BOFF  18432
#define G1_STAGE 36864
#define G1_SMEM  (3 * G1_STAGE)

__global__ void __launch_bounds__(256, 2) gemm1_mma(
    const float* __restrict__ x, const float* __restrict__ bfp)
{
    extern __shared__ char smch[];
    const uint32_t sb = smem_u32(smch);
    const int tid  = threadIdx.x;
    const int warp = tid >> 5, lane = tid & 31;
    const int gr = lane >> 2, tg = lane & 3;
    const int n0 = blockIdx.x * 128;
    const int m0 = blockIdx.y * 128;
    const int wm = (warp >> 2) * 64, wn = (warp & 3) * 32;

    // per-lane ldmatrix address components
    const uint32_t laneA = (uint32_t)(((lane & 7) + ((lane >> 3) & 1) * 8) * 144
                                      + ((lane >> 4) & 1) * 16);
    const uint32_t laneB = (uint32_t)((lane & 7) * 144 + ((lane >> 3) & 1) * 16);

    auto issue = [&](int ks, int st) {
        const uint32_t base = sb + st * G1_STAGE;
#pragma unroll
        for (int i = 0; i < 4; i++) {
            int idx = tid + i * 256;
            int row = idx >> 3, c4 = idx & 7;
            cp16(base + row * 144 + c4 * 16,
                 x + (size_t)(m0 + row) * DIN + ks * 32 + c4 * 4);
        }
#pragma unroll
        for (int i = 0; i < 4; i++) {
            int idx = tid + i * 256;
            int row = idx >> 3, c4 = idx & 7;
            cp16(base + G1_BOFF + row * 144 + c4 * 16,
                 g_Wtf + (size_t)(n0 + row) * DIN + ks * 32 + c4 * 4);
        }
    };

    float acc[4][4][4];
#pragma unroll
    for (int a = 0; a < 4; a++)
#pragma unroll
        for (int b = 0; b < 4; b++)
#pragma unroll
            for (int c = 0; c < 4; c++) acc[a][b][c] = 0.f;

    issue(0, 0); CP_COMMIT();
    issue(1, 1); CP_COMMIT();

    for (int ks = 0; ks < 32; ks++) {
        CP_WAIT1();
        __syncthreads();
        if (ks + 2 < 32) issue(ks + 2, (ks + 2) % 3);
        CP_COMMIT();
        const uint32_t sA = sb + (ks % 3) * G1_STAGE;
        const uint32_t sB = sA + G1_BOFF;
#pragma unroll
        for (int kk = 0; kk < 4; kk++) {
            const int kb = kk * 8;
            const uint32_t Ab = sA + kb * 4 + laneA;
            const uint32_t Bb = sB + kb * 4 + laneB;
            uint32_t af[4][4];
#pragma unroll
            for (int mf = 0; mf < 4; mf++)
                ldsm4(af[mf][0], af[mf][1], af[mf][2], af[mf][3],
                      Ab + (wm + mf * 16) * 144);
            uint32_t bfr[4][2];
#pragma unroll
            for (int nf = 0; nf < 4; nf++)
                ldsm2(bfr[nf][0], bfr[nf][1], Bb + (wn + nf * 8) * 144);
#pragma unroll
            for (int mf = 0; mf < 4; mf++)
#pragma unroll
                for (int nf = 0; nf < 4; nf++)
                    mma8(acc[mf][nf][0], acc[mf][nf][1], acc[mf][nf][2], acc[mf][nf][3],
                         af[mf][0], af[mf][1], af[mf][2], af[mf][3],
                         bfr[nf][0], bfr[nf][1]);
        }
    }

    // Epilogue: bias + relu, store fp32
#pragma unroll
    for (int mf = 0; mf < 4; mf++) {
        const int r0 = m0 + wm + mf * 16 + gr;
#pragma unroll
        for (int nf = 0; nf < 4; nf++) {
            const int n = n0 + wn + nf * 8 + 2 * tg;
            const float b0v = bfp[n], b1v = bfp[n + 1];
            float2 v0, v1;
            v0.x = fmaxf(acc[mf][nf][0] + b0v, 0.f);
            v0.y = fmaxf(acc[mf][nf][1] + b1v, 0.f);
            v1.x = fmaxf(acc[mf][nf][2] + b0v, 0.f);
            v1.y = fmaxf(acc[mf][nf][3] + b1v, 0.f);
            *(float2*)&g_h[(size_t)r0 * LDIM + n] = v0;
            *(float2*)&g_h[(size_t)(r0 + 8) * LDIM + n] = v1;
        }
    }
}

// ---------------------------------------------------------------------------
// GEMM2 (fused): per (d-tile 64, m-tile 128): acca = h@Wa, accg = h@Wb,
// spart[row] = sum_d tanh(acca+ba)*sigmoid(accg+bb)*wc.
// 8 warps (4m x 2n), warp tile 32x32, dual accumulators.
// ---------------------------------------------------------------------------
#define G2_BAOFF 18432
#define G2_BBOFF 27648
#define G2_STAGE 36864
#define G2_SMEM  (3 * G2_STAGE)

__global__ void __launch_bounds__(256, 2) gemm2_mma(
    const float* __restrict__ ba, const float* __restrict__ bb,
    const float* __restrict__ Wc)
{
    extern __shared__ char smch[];
    __shared__ float red[256];
    const uint32_t sb = smem_u32(smch);
    const int tid  = threadIdx.x;
    const int warp = tid >> 5, lane = tid & 31;
    const int gr = lane >> 2, tg = lane & 3;
    const int n0 = blockIdx.x * 64;
    const int m0 = blockIdx.y * 128;
    const int wm = (warp >> 1) * 32, wn = (warp & 1) * 32;

    const uint32_t laneA = (uint32_t)(((lane & 7) + ((lane >> 3) & 1) * 8) * 144
                                      + ((lane >> 4) & 1) * 16);
    const uint32_t laneB = (uint32_t)((lane & 7) * 144 + ((lane >> 3) & 1) * 16);

    auto issue = [&](int ks, int st) {
        const uint32_t base = sb + st * G2_STAGE;
        // A tile: 128 rows x 32k = 1024 float4
#pragma unroll
        for (int i = 0; i < 4; i++) {
            int idx = tid + i * 256;
            int row = idx >> 3, c4 = idx & 7;
            cp16(base + row * 144 + c4 * 16,
                 g_h + (size_t)(m0 + row) * LDIM + ks * 32 + c4 * 4);
        }
        // B tiles: Ba then Bb, each 64 rows x 32k = 512 float4 (1024 total)
#pragma unroll
        for (int i = 0; i < 4; i++) {
            int idx = tid + i * 256;        // 0..1023
            int half = idx >> 9;            // 0 -> Ba, 1 -> Bb
            int sub = idx & 511;
            int row = sub >> 3, c4 = sub & 7;
            const float* src = half ? (g_Wtb + (size_t)(n0 + row) * LDIM + ks * 32 + c4 * 4)
                                    : (g_Wta + (size_t)(n0 + row) * LDIM + ks * 32 + c4 * 4);
            cp16(base + (half ? G2_BBOFF : G2_BAOFF) + row * 144 + c4 * 16, src);
        }
    };

    float acca[2][4][4], accg[2][4][4];
#pragma unroll
    for (int a = 0; a < 2; a++)
#pragma unroll
        for (int b = 0; b < 4; b++)
#pragma unroll
            for (int c = 0; c < 4; c++) { acca[a][b][c] = 0.f; accg[a][b][c] = 0.f; }

    issue(0, 0); CP_COMMIT();
    issue(1, 1); CP_COMMIT();

    for (int ks = 0; ks < 16; ks++) {
        CP_WAIT1();
        __syncthreads();
        if (ks + 2 < 16) issue(ks + 2, (ks + 2) % 3);
        CP_COMMIT();
        const uint32_t sA  = sb + (ks % 3) * G2_STAGE;
        const uint32_t sBa = sA + G2_BAOFF;
        const uint32_t sBb = sA + G2_BBOFF;
#pragma unroll
        for (int kk = 0; kk < 4; kk++) {
            const int kb = kk * 8;
            const uint32_t Ab  = sA + kb * 4 + laneA;
            const uint32_t Bab = sBa + kb * 4 + laneB;
            const uint32_t Bbb = sBb + kb * 4 + laneB;
            uint32_t af[2][4];
#pragma unroll
            for (int mf = 0; mf < 2; mf++)
                ldsm4(af[mf][0], af[mf][1], af[mf][2], af[mf][3],
                      Ab + (wm + mf * 16) * 144);
            uint32_t bafr[4][2], bbfr[4][2];
#pragma unroll
            for (int nf = 0; nf < 4; nf++) {
                ldsm2(bafr[nf][0], bafr[nf][1], Bab + (wn + nf * 8) * 144);
                ldsm2(bbfr[nf][0], bbfr[nf][1], Bbb + (wn + nf * 8) * 144);
            }
#pragma unroll
            for (int mf = 0; mf < 2; mf++)
#pragma unroll
                for (int nf = 0; nf < 4; nf++) {
                    mma8(acca[mf][nf][0], acca[mf][nf][1], acca[mf][nf][2], acca[mf][nf][3],
                         af[mf][0], af[mf][1], af[mf][2], af[mf][3],
                         bafr[nf][0], bafr[nf][1]);
                    mma8(accg[mf][nf][0], accg[mf][nf][1], accg[mf][nf][2], accg[mf][nf][3],
                         af[mf][0], af[mf][1], af[mf][2], af[mf][3],
                         bbfr[nf][0], bbfr[nf][1]);
                }
        }
    }

    // Epilogue: tanh*sigmoid*wc, reduce over 64 d-cols
    float bav[4][2], bbv[4][2], wcv[4][2];
#pragma unroll
    for (int nf = 0; nf < 4; nf++) {
        const int d = n0 + wn + nf * 8 + 2 * tg;
        bav[nf][0] = ba[d]; bav[nf][1] = ba[d + 1];
        bbv[nf][0] = bb[d]; bbv[nf][1] = bb[d + 1];
        wcv[nf][0] = Wc[d]; wcv[nf][1] = Wc[d + 1];
    }
#pragma unroll
    for (int mf = 0; mf < 2; mf++) {
#pragma unroll
        for (int h = 0; h < 2; h++) {
            float s = 0.f;
#pragma unroll
            for (int nf = 0; nf < 4; nf++) {
#pragma unroll
                for (int c = 0; c < 2; c++) {
                    const float av = tanhf(acca[mf][nf][h * 2 + c] + bav[nf][c]);
                    const float gv = 1.f / (1.f + expf(-(accg[mf][nf][h * 2 + c] + bbv[nf][c])));
                    s = fmaf(av * gv, wcv[nf][c], s);
                }
            }
            s += __shfl_xor_sync(0xFFFFFFFF, s, 1);
            s += __shfl_xor_sync(0xFFFFFFFF, s, 2);
            if (tg == 0)
                red[(wm + mf * 16 + h * 8 + gr) * 2 + (warp & 1)] = s;
        }
    }
    __syncthreads();
    if (tid < 128)
        g_spart[(size_t)blockIdx.x * MTOT + m0 + tid] = red[tid * 2] + red[tid * 2 + 1];
}

// ---------------------------------------------------------------------------
// Tail kernels
// ---------------------------------------------------------------------------
__global__ void sred_kernel(const float* __restrict__ bc)
{
    __shared__ float sm[256];
    const int b = blockIdx.y, tid = threadIdx.x;
    const int n = blockIdx.x * 256 + tid;
    float v = -3.4e38f;
    if (n < NPB) {
        const int gm = b * NPB + n;
        float s = bc[0];
#pragma unroll
        for (int t = 0; t < NDT; t++) s += g_spart[(size_t)t * MTOT + gm];
        g_s[gm] = s;
        v = s;
    }
    sm[tid] = v;
    __syncthreads();
    for (int o = 128; o > 0; o >>= 1) {
        if (tid < o) sm[tid] = fmaxf(sm[tid], sm[tid + o]);
        __syncthreads();
    }
    if (tid == 0) g_bmax[b * NCHUNK + blockIdx.x] = sm[0];
}

__global__ void maxfin_kernel()
{
    __shared__ float sm[256];
    const int b = blockIdx.x, tid = threadIdx.x;
    sm[tid] = (tid < NCHUNK) ? g_bmax[b * NCHUNK + tid] : -3.4e38f;
    __syncthreads();
    for (int o = 128; o > 0; o >>= 1) {
        if (tid < o) sm[tid] = fmaxf(sm[tid], sm[tid + o]);
        __syncthreads();
    }
    if (tid == 0) g_maxv[b] = sm[0];
}

__global__ void __launch_bounds__(256) pool_kernel()
{
    __shared__ float esh[256];
    __shared__ float zr[256];
    const int b = blockIdx.y, cx = blockIdx.x, tid = threadIdx.x;
    const int base = cx * 256;
    const int n = base + tid;
    float e = 0.f;
    if (n < NPB) e = expf(g_s[b * NPB + n] - g_maxv[b]);
    esh[tid] = e;
    zr[tid]  = e;
    __syncthreads();
    for (int o = 128; o > 0; o >>= 1) {
        if (tid < o) zr[tid] += zr[tid + o];
        __syncthreads();
    }
    if (tid == 0) g_Zpart[b * NCHUNK + cx] = zr[0];

    const int rmax = min(256, NPB - base);
    const int c = tid * 2;
    const float* hb = g_h + ((size_t)b * NPB + base) * LDIM + c;
    float ax = 0.f, ay = 0.f;
    for (int r = 0; r < rmax; r++) {
        const float w = esh[r];
        float2 hv = *(const float2*)(hb + (size_t)r * LDIM);
        ax = fmaf(w, hv.x, ax);
        ay = fmaf(w, hv.y, ay);
    }
    float* up = g_Upart + (size_t)(b * NCHUNK + cx) * LDIM + c;
    up[0] = ax;
    up[1] = ay;
}

__global__ void final_kernel(const float* __restrict__ Wcls,
                             const float* __restrict__ bcls,
                             float* __restrict__ out)
{
    __shared__ float r0[512], r1[512];
    const int b = blockIdx.x, l = threadIdx.x;
    float U = 0.f;
    for (int c = 0; c < NCHUNK; c++)
        U += g_Upart[(size_t)(b * NCHUNK + c) * LDIM + l];
    float Z = 0.f;
    for (int c = 0; c < NCHUNK; c++) Z += g_Zpart[b * NCHUNK + c];
    const float p = U / Z;
    r0[l] = p * Wcls[l * 2 + 0];
    r1[l] = p * Wcls[l * 2 + 1];
    __syncthreads();
    for (int o = 256; o > 0; o >>= 1) {
        if (l < o) { r0[l] += r0[l + o]; r1[l] += r1[l + o]; }
        __syncthreads();
    }
    if (l == 0) {
        out[b * 2 + 0] = r0[0] + bcls[0];
        out[b * 2 + 1] = r1[0] + bcls[1];
    }
}

// ---------------------------------------------------------------------------
extern "C" void kernel_launch(void* const* d_in, const int* in_sizes, int n_in,
                              void* d_out, int out_size)
{
    const float* x    = (const float*)d_in[0];
    const float* Wf   = (const float*)d_in[1];
    const float* bf   = (const float*)d_in[2];
    const float* Wa   = (const float*)d_in[3];
    const float* ba   = (const float*)d_in[4];
    const float* Wb   = (const float*)d_in[5];
    const float* bb   = (const float*)d_in[6];
    const float* Wc   = (const float*)d_in[7];
    const float* bc   = (const float*)d_in[8];
    const float* Wcls = (const float*)d_in[9];
    const float* bcls = (const float*)d_in[10];
    float* out = (float*)d_out;

    cudaFuncSetAttribute(gemm1_mma, cudaFuncAttributeMaxDynamicSharedMemorySize, G1_SMEM);
    cudaFuncSetAttribute(gemm2_mma, cudaFuncAttributeMaxDynamicSharedMemorySize, G2_SMEM);

    prep_w<<<2048, 256>>>(Wf, Wa, Wb);

    dim3 g1(LDIM / 128, MTOT / 128);      // (4, 625)
    gemm1_mma<<<g1, 256, G1_SMEM>>>(x, bf);

    dim3 g2(DDIM / 64, MTOT / 128);       // (6, 625)
    gemm2_mma<<<g2, 256, G2_SMEM>>>(ba, bb, Wc);

    dim3 g3(NCHUNK, NBATCH);
    sred_kernel<<<g3, 256>>>(bc);
    maxfin_kernel<<<NBATCH, 256>>>();
    pool_kernel<<<g3, 256>>>();
    final_kernel<<<NBATCH, 512>>>(Wcls, bcls, out);
}